// round 9
// baseline (speedup 1.0000x reference)
#include <cuda_runtime.h>
#include <cstdint>

#define Bsz 8
#define Nn 2048
#define FIN 128
#define FO 64
#define ALPHA 0.2f

#define BM 32
#define BN 64
#define NTILES (Nn / BN)   // 32

// Scratch device globals (allocation-free per harness rules)
__device__ float g_WhT[Bsz * FO * Nn];   // transposed: [b][o][n]
__device__ float g_e1[Bsz * Nn];
__device__ float g_e2[Bsz * Nn];

// ---------------------------------------------------------------------------
// helpers
// ---------------------------------------------------------------------------
static __device__ __forceinline__ float tf32r(float x) {
    uint32_t u;
    asm("cvt.rna.tf32.f32 %0, %1;" : "=r"(u) : "f"(x));
    return __uint_as_float(u);
}

static __device__ __forceinline__ void mma_tf32(
    float* d, const uint32_t* a, uint32_t b0, uint32_t b1)
{
    asm volatile(
        "mma.sync.aligned.m16n8k8.row.col.f32.tf32.tf32.f32 "
        "{%0,%1,%2,%3},{%4,%5,%6,%7},{%8,%9},{%0,%1,%2,%3};"
        : "+f"(d[0]), "+f"(d[1]), "+f"(d[2]), "+f"(d[3])
        : "r"(a[0]), "r"(a[1]), "r"(a[2]), "r"(a[3]), "r"(b0), "r"(b1));
}

// ---------------------------------------------------------------------------
// Kernel 1: Wh = h @ W (written TRANSPOSED as WhT[b][o][n]); e1 = Wh·a1; e2 = Wh·a2
// ---------------------------------------------------------------------------
__global__ __launch_bounds__(256) void gat_proj_kernel(
    const float* __restrict__ h,
    const float* __restrict__ W,
    const float* __restrict__ a)
{
    __shared__ float sW[FIN * FO];   // 32 KB
    __shared__ float sT[FO * 33];    // transpose staging, pitch 33

    const int t = threadIdx.x;
#pragma unroll
    for (int r = 0; r < 8; r++)
        *(float4*)&sW[r * 1024 + t * 4] = *(const float4*)&W[r * 1024 + t * 4];

    const int warp = t >> 5;
    const int lane = t & 31;
    const int g0 = blockIdx.x * 32;
    const int i0 = g0 + warp * 4;

    const float a1l = a[lane];
    const float a1h = a[lane + 32];
    const float a2l = a[FO + lane];
    const float a2h = a[FO + 32 + lane];

    __syncthreads();

    float hr[4][4];
#pragma unroll
    for (int r = 0; r < 4; r++) {
        const float* hp = h + (long)(i0 + r) * FIN;
#pragma unroll
        for (int q = 0; q < 4; q++) hr[r][q] = hp[q * 32 + lane];
    }

    float acc[4][2];
#pragma unroll
    for (int r = 0; r < 4; r++) { acc[r][0] = 0.f; acc[r][1] = 0.f; }

#pragma unroll
    for (int q = 0; q < 4; q++) {
#pragma unroll
        for (int kk = 0; kk < 32; kk++) {
            const int k = q * 32 + kk;
            const float w0 = sW[k * FO + lane];
            const float w1 = sW[k * FO + 32 + lane];
#pragma unroll
            for (int r = 0; r < 4; r++) {
                const float hv = __shfl_sync(0xffffffffu, hr[r][q], kk);
                acc[r][0] = fmaf(hv, w0, acc[r][0]);
                acc[r][1] = fmaf(hv, w1, acc[r][1]);
            }
        }
    }

#pragma unroll
    for (int r = 0; r < 4; r++) {
        sT[lane * 33 + warp * 4 + r]        = acc[r][0];
        sT[(lane + 32) * 33 + warp * 4 + r] = acc[r][1];
    }

#pragma unroll
    for (int r = 0; r < 4; r++) {
        float e1 = acc[r][0] * a1l + acc[r][1] * a1h;
        float e2 = acc[r][0] * a2l + acc[r][1] * a2h;
#pragma unroll
        for (int off = 16; off > 0; off >>= 1) {
            e1 += __shfl_xor_sync(0xffffffffu, e1, off);
            e2 += __shfl_xor_sync(0xffffffffu, e2, off);
        }
        if (lane == 0) {
            g_e1[i0 + r] = e1;
            g_e2[i0 + r] = e2;
        }
    }

    __syncthreads();

    const int bb = g0 >> 11;
    const int il = g0 & (Nn - 1);
    const int oB = t >> 3;
    const int ii = (t & 7) * 4;
#pragma unroll
    for (int hf = 0; hf < 2; hf++) {
        const int o = hf * 32 + oB;
        float4 v;
        v.x = sT[o * 33 + ii + 0];
        v.y = sT[o * 33 + ii + 1];
        v.z = sT[o * 33 + ii + 2];
        v.w = sT[o * 33 + ii + 3];
        *(float4*)&g_WhT[((long)(bb * FO + o)) * Nn + il + ii] = v;
    }
}

// ---------------------------------------------------------------------------
// Kernel 2: masked-softmax aggregation via mma.sync tf32 (no-max softmax).
// grid (64, 8) = 512 CTAs, 256 threads. BN=64 tiles, double-buffered smem,
// 2-deep register prefetch (two explicit stages, manually unrolled x2).
// ---------------------------------------------------------------------------

struct StageRegs {
    int4   av[2];
    float4 e2v[2];
    float4 vv[4];
};

static __device__ __forceinline__ void stage_load(
    StageRegs& s, int j0,
    const int* __restrict__ adjRow, const float* __restrict__ e2p,
    const float* __restrict__ vsrc)
{
    s.av[0]  = *(const int4*)(adjRow + j0);
    s.av[1]  = *(const int4*)(adjRow + j0 + 4);
    s.e2v[0] = *(const float4*)(e2p + j0);
    s.e2v[1] = *(const float4*)(e2p + j0 + 4);
#pragma unroll
    for (int g = 0; g < 4; g++)
        s.vv[g] = *(const float4*)(vsrc + j0 + g * 4);
}

__global__ __launch_bounds__(256) void gat_agg_mma_kernel(
    const int* __restrict__ adj,
    float* __restrict__ out)
{
    __shared__ __align__(16) float sP[2][BM * BN];    // 16 KB, 64-word swizzled rows
    __shared__ __align__(16) float sVT[2][FO * BN];   // 32 KB
    float* sS = &sVT[0][0];   // row sums aliased onto sVT[0] (dead at epilogue)

    const int b  = blockIdx.y;
    const int i0 = blockIdx.x * BM;
    const int t  = threadIdx.x;
    const int warp = t >> 5;
    const int lane = t & 31;

    // score mapping: thread <-> (row, 8 j's)
    const int rowi = t >> 3;            // 0..31
    const int jq   = (t & 7) * 8;       // 0..56
    const float e1i = g_e1[b * Nn + i0 + rowi];
    const int*   adjRow = adj + ((long)(b * Nn + i0 + rowi)) * Nn + jq;
    const float* e2p    = g_e2 + b * Nn + jq;

    // V staging: thread <-> (o, 16 j's)
    const int vo = t >> 2;              // 0..63
    const int vq = (t & 3) * 16;        // 0..48
    const float* vsrc = g_WhT + ((long)(b * FO + vo)) * Nn + vq;

    // matmul mapping: warp tile 16 rows x 16 cols
    const int wm = warp & 1;
    const int wn = warp >> 1;           // 0..3
    const int lq = lane >> 2;
    const int lr = lane & 3;

    float acc[2][4];
#pragma unroll
    for (int n = 0; n < 2; n++)
#pragma unroll
        for (int r = 0; r < 4; r++) acc[n][r] = 0.f;

    float ssum = 0.f;

    StageRegs stA, stB;
    stage_load(stA, 0, adjRow, e2p, vsrc);
    stage_load(stB, BN, adjRow, e2p, vsrc);

#define TILE_BODY(TILE, ST, OTHERLOADTILE)                                       \
    {                                                                            \
        const int buf = (TILE) & 1;                                              \
        /* scores */                                                             \
        float pv[8];                                                             \
        _Pragma("unroll")                                                        \
        for (int g = 0; g < 2; g++) {                                            \
            const int4   aa = ST.av[g];                                          \
            const float4 ee = ST.e2v[g];                                         \
            float x;                                                             \
            x = e1i + ee.x; x = fmaxf(x, ALPHA * x);                             \
            pv[g*4+0] = (aa.x > 0) ? tf32r(__expf(x)) : 0.f;                     \
            x = e1i + ee.y; x = fmaxf(x, ALPHA * x);                             \
            pv[g*4+1] = (aa.y > 0) ? tf32r(__expf(x)) : 0.f;                     \
            x = e1i + ee.z; x = fmaxf(x, ALPHA * x);                             \
            pv[g*4+2] = (aa.z > 0) ? tf32r(__expf(x)) : 0.f;                     \
            x = e1i + ee.w; x = fmaxf(x, ALPHA * x);                             \
            pv[g*4+3] = (aa.w > 0) ? tf32r(__expf(x)) : 0.f;                     \
            ssum += (pv[g*4+0] + pv[g*4+1]) + (pv[g*4+2] + pv[g*4+3]);           \
        }                                                                        \
        /* P store, swizzle word = (r<<6) + ((c + 4r)&63) */                     \
        *(float4*)&sP[buf][(rowi << 6) + ((jq     + (rowi << 2)) & 63)] =        \
            make_float4(pv[0], pv[1], pv[2], pv[3]);                             \
        *(float4*)&sP[buf][(rowi << 6) + ((jq + 4 + (rowi << 2)) & 63)] =        \
            make_float4(pv[4], pv[5], pv[6], pv[7]);                             \
        /* V store */                                                            \
        _Pragma("unroll")                                                        \
        for (int g = 0; g < 4; g++)                                              \
            *(float4*)&sVT[buf][(vo << 6) + ((vq + g * 4 + (vo << 2)) & 63)] =   \
                ST.vv[g];                                                        \
        __syncthreads();                                                         \
        /* prefetch 2 tiles ahead into this stage */                             \
        if ((OTHERLOADTILE) < NTILES)                                            \
            stage_load(ST, (OTHERLOADTILE) * BN, adjRow, e2p, vsrc);             \
        /* MMA: 8 k-steps x 2 n-tiles */                                         \
        const float* cP = &sP[buf][0];                                           \
        const float* cV = &sVT[buf][0];                                          \
        _Pragma("unroll")                                                        \
        for (int k = 0; k < 8; k++) {                                            \
            uint32_t afr[4];                                                     \
            const int r0 = wm * 16 + lq;                                         \
            const int r1 = r0 + 8;                                               \
            const int c0 = k * 8 + lr;                                           \
            afr[0] = __float_as_uint(cP[(r0 << 6) + ((c0     + (r0 << 2)) & 63)]); \
            afr[1] = __float_as_uint(cP[(r1 << 6) + ((c0     + (r1 << 2)) & 63)]); \
            afr[2] = __float_as_uint(cP[(r0 << 6) + ((c0 + 4 + (r0 << 2)) & 63)]); \
            afr[3] = __float_as_uint(cP[(r1 << 6) + ((c0 + 4 + (r1 << 2)) & 63)]); \
            _Pragma("unroll")                                                    \
            for (int nt = 0; nt < 2; nt++) {                                     \
                const int o  = wn * 16 + nt * 8 + lq;                            \
                const int jb = k * 8 + lr;                                       \
                const uint32_t b0 =                                              \
                    __float_as_uint(cV[(o << 6) + ((jb     + (o << 2)) & 63)]);  \
                const uint32_t b1 =                                              \
                    __float_as_uint(cV[(o << 6) + ((jb + 4 + (o << 2)) & 63)]);  \
                mma_tf32(acc[nt], afr, b0, b1);                                  \
            }                                                                    \
        }                                                                        \
    }

    for (int tp = 0; tp < NTILES; tp += 2) {
        TILE_BODY(tp,     stA, tp + 2);
        TILE_BODY(tp + 1, stB, tp + 3);
    }
#undef TILE_BODY

    // ---- row sums: reduce over 8 threads sharing a row ----
    ssum += __shfl_xor_sync(0xffffffffu, ssum, 1);
    ssum += __shfl_xor_sync(0xffffffffu, ssum, 2);
    ssum += __shfl_xor_sync(0xffffffffu, ssum, 4);
    __syncthreads();               // all MMA reads of sVT done before aliasing
    if ((t & 7) == 0) sS[rowi] = ssum;
    __syncthreads();

    // ---- epilogue: normalize, ELU, store ----
    {
        const int r0 = wm * 16 + lq;
        const int r1 = r0 + 8;
        const float inv0 = 1.0f / sS[r0];
        const float inv1 = 1.0f / sS[r1];
        float* o0 = out + ((long)(b * Nn + i0 + r0)) * FO;
        float* o1 = out + ((long)(b * Nn + i0 + r1)) * FO;
#pragma unroll
        for (int nt = 0; nt < 2; nt++) {
            const int col = wn * 16 + nt * 8 + lr * 2;
            float2 q0, q1;
            float x;
            x = acc[nt][0] * inv0; q0.x = (x > 0.f) ? x : expm1f(x);
            x = acc[nt][1] * inv0; q0.y = (x > 0.f) ? x : expm1f(x);
            x = acc[nt][2] * inv1; q1.x = (x > 0.f) ? x : expm1f(x);
            x = acc[nt][3] * inv1; q1.y = (x > 0.f) ? x : expm1f(x);
            *(float2*)(o0 + col) = q0;
            *(float2*)(o1 + col) = q1;
        }
    }
}

// ---------------------------------------------------------------------------
extern "C" void kernel_launch(void* const* d_in, const int* in_sizes, int n_in,
                              void* d_out, int out_size)
{
    const float* h   = (const float*)d_in[0];
    const int*   adj = (const int*)d_in[1];
    const float* W   = (const float*)d_in[2];
    const float* a   = (const float*)d_in[3];
    float* out = (float*)d_out;

    gat_proj_kernel<<<(Bsz * Nn) / 32, 256>>>(h, W, a);
    gat_agg_mma_kernel<<<dim3(Nn / BM, Bsz), 256>>>(adj, out);
}

// round 11
// speedup vs baseline: 1.9506x; 1.9506x over previous
#include <cuda_runtime.h>
#include <cstdint>

#define Bsz 8
#define Nn 2048
#define FIN 128
#define FO 64
#define ALPHA 0.2f

#define BM 32
#define BN 32
#define NTILES (Nn / BN)   // 64
#define NS 3               // cp.async pipeline stages

// Scratch device globals (allocation-free per harness rules)
__device__ float g_WhT[Bsz * FO * Nn];   // transposed: [b][o][n]
__device__ float g_e1[Bsz * Nn];
__device__ float g_e2[Bsz * Nn];

// ---------------------------------------------------------------------------
// helpers
// ---------------------------------------------------------------------------
static __device__ __forceinline__ uint32_t smem_u32(const void* p) {
    uint32_t a;
    asm("{ .reg .u64 t; cvta.to.shared.u64 t, %1; cvt.u32.u64 %0, t; }"
        : "=r"(a) : "l"(p));
    return a;
}
static __device__ __forceinline__ void cp16(uint32_t dst, const void* src) {
    asm volatile("cp.async.cg.shared.global [%0], [%1], 16;"
                 :: "r"(dst), "l"(src) : "memory");
}
#define CP_COMMIT() asm volatile("cp.async.commit_group;" ::: "memory")
#define CP_WAIT1()  asm volatile("cp.async.wait_group 1;" ::: "memory")

static __device__ __forceinline__ float tf32r(float x) {
    uint32_t u;
    asm("cvt.rna.tf32.f32 %0, %1;" : "=r"(u) : "f"(x));
    return __uint_as_float(u);
}

static __device__ __forceinline__ void mma_tf32(
    float* d, const uint32_t* a, uint32_t b0, uint32_t b1)
{
    asm volatile(
        "mma.sync.aligned.m16n8k8.row.col.f32.tf32.tf32.f32 "
        "{%0,%1,%2,%3},{%4,%5,%6,%7},{%8,%9},{%0,%1,%2,%3};"
        : "+f"(d[0]), "+f"(d[1]), "+f"(d[2]), "+f"(d[3])
        : "r"(a[0]), "r"(a[1]), "r"(a[2]), "r"(a[3]), "r"(b0), "r"(b1));
}

// ---------------------------------------------------------------------------
// Kernel 1: Wh = h @ W (written TRANSPOSED as WhT[b][o][n]); e1 = Wh·a1; e2 = Wh·a2
// ---------------------------------------------------------------------------
__global__ __launch_bounds__(256) void gat_proj_kernel(
    const float* __restrict__ h,
    const float* __restrict__ W,
    const float* __restrict__ a)
{
    __shared__ float sW[FIN * FO];   // 32 KB
    __shared__ float sT[FO * 33];    // transpose staging, pitch 33

    const int t = threadIdx.x;
#pragma unroll
    for (int r = 0; r < 8; r++)
        *(float4*)&sW[r * 1024 + t * 4] = *(const float4*)&W[r * 1024 + t * 4];

    const int warp = t >> 5;
    const int lane = t & 31;
    const int g0 = blockIdx.x * 32;
    const int i0 = g0 + warp * 4;

    const float a1l = a[lane];
    const float a1h = a[lane + 32];
    const float a2l = a[FO + lane];
    const float a2h = a[FO + 32 + lane];

    __syncthreads();

    float hr[4][4];
#pragma unroll
    for (int r = 0; r < 4; r++) {
        const float* hp = h + (long)(i0 + r) * FIN;
#pragma unroll
        for (int q = 0; q < 4; q++) hr[r][q] = hp[q * 32 + lane];
    }

    float acc[4][2];
#pragma unroll
    for (int r = 0; r < 4; r++) { acc[r][0] = 0.f; acc[r][1] = 0.f; }

#pragma unroll
    for (int q = 0; q < 4; q++) {
#pragma unroll
        for (int kk = 0; kk < 32; kk++) {
            const int k = q * 32 + kk;
            const float w0 = sW[k * FO + lane];
            const float w1 = sW[k * FO + 32 + lane];
#pragma unroll
            for (int r = 0; r < 4; r++) {
                const float hv = __shfl_sync(0xffffffffu, hr[r][q], kk);
                acc[r][0] = fmaf(hv, w0, acc[r][0]);
                acc[r][1] = fmaf(hv, w1, acc[r][1]);
            }
        }
    }

#pragma unroll
    for (int r = 0; r < 4; r++) {
        sT[lane * 33 + warp * 4 + r]        = acc[r][0];
        sT[(lane + 32) * 33 + warp * 4 + r] = acc[r][1];
    }

#pragma unroll
    for (int r = 0; r < 4; r++) {
        float e1 = acc[r][0] * a1l + acc[r][1] * a1h;
        float e2 = acc[r][0] * a2l + acc[r][1] * a2h;
#pragma unroll
        for (int off = 16; off > 0; off >>= 1) {
            e1 += __shfl_xor_sync(0xffffffffu, e1, off);
            e2 += __shfl_xor_sync(0xffffffffu, e2, off);
        }
        if (lane == 0) {
            g_e1[i0 + r] = e1;
            g_e2[i0 + r] = e2;
        }
    }

    __syncthreads();

    const int bb = g0 >> 11;
    const int il = g0 & (Nn - 1);
    const int oB = t >> 3;
    const int ii = (t & 7) * 4;
#pragma unroll
    for (int hf = 0; hf < 2; hf++) {
        const int o = hf * 32 + oB;
        float4 v;
        v.x = sT[o * 33 + ii + 0];
        v.y = sT[o * 33 + ii + 1];
        v.z = sT[o * 33 + ii + 2];
        v.w = sT[o * 33 + ii + 3];
        *(float4*)&g_WhT[((long)(bb * FO + o)) * Nn + il + ii] = v;
    }
}

// ---------------------------------------------------------------------------
// Kernel 2: masked-softmax aggregation via mma.sync tf32 (no-max softmax).
// grid (64, 8) = 512 CTAs, 256 threads. 3-stage cp.async pipeline for adj + V,
// one barrier per tile, forced 4 CTAs/SM.
// ---------------------------------------------------------------------------
__global__ __launch_bounds__(256, 4) void gat_agg_mma_kernel(
    const int* __restrict__ adj,
    float* __restrict__ out)
{
    __shared__ __align__(16) int   sAdj[NS][BM * BN];   // 12 KB
    __shared__ __align__(16) float sVT[NS][FO * BN];    // 24 KB (XOR-swizzled)
    __shared__ __align__(16) float sP[2][BM * BN];      // 8 KB  (additive-swizzled)
    __shared__ float sS[BM];

    const int b  = blockIdx.y;
    const int i0 = blockIdx.x * BM;
    const int t  = threadIdx.x;
    const int warp = t >> 5;
    const int lane = t & 31;

    // score mapping: thread <-> (row, 4 j's)
    const int rowi = t >> 3;            // 0..31
    const int jq   = (t & 7) * 4;       // 0..28
    const float e1i = g_e1[b * Nn + i0 + rowi];
    const int*   adjRow = adj + ((long)(b * Nn + i0 + rowi)) * Nn + jq;
    const float* e2p    = g_e2 + b * Nn + jq;

    // V staging: thread <-> (o, 8 j's)
    const int vo = t >> 2;              // 0..63
    const int vq = (t & 3) * 8;         // 0..24
    const int vsw = (vo & 7) << 2;
    const float* vsrc = g_WhT + ((long)(b * FO + vo)) * Nn + vq;

    // per-thread fixed smem dst addresses
    const uint32_t adjDst = smem_u32(&sAdj[0][0]) + (uint32_t)((rowi * BN + jq) * 4);
    const uint32_t vDst0  = smem_u32(&sVT[0][0]) + (uint32_t)(((vo << 5) + (vq ^ vsw)) * 4);
    const uint32_t vDst1  = smem_u32(&sVT[0][0]) + (uint32_t)(((vo << 5) + ((vq + 4) ^ vsw)) * 4);

    // matmul mapping: warp tile 16 rows x 16 cols
    const int wm = warp & 1;
    const int wn = warp >> 1;           // 0..3
    const int lq = lane >> 2;
    const int lr = lane & 3;

    float acc[2][4];
#pragma unroll
    for (int n = 0; n < 2; n++)
#pragma unroll
        for (int r = 0; r < 4; r++) acc[n][r] = 0.f;

    float ssum = 0.f;

    // ---- prologue: issue stages for tiles 0, 1 ----
#pragma unroll
    for (int s = 0; s < NS - 1; s++) {
        cp16(adjDst + (uint32_t)(s * BM * BN * 4), adjRow + s * BN);
        cp16(vDst0 + (uint32_t)(s * FO * BN * 4), vsrc + s * BN);
        cp16(vDst1 + (uint32_t)(s * FO * BN * 4), vsrc + s * BN + 4);
        CP_COMMIT();
    }
    float4 e2cur = *(const float4*)(e2p);

    int stg = 0;        // stage of current tile
    int stgI = NS - 1;  // stage being filled this iteration (tile t+NS-1)

    for (int tile = 0; tile < NTILES; tile++) {
        const int buf = tile & 1;

        // prefetch next tile's e2 into registers (L2-resident, tiny)
        float4 e2nxt;
        if (tile < NTILES - 1) e2nxt = *(const float4*)(e2p + (tile + 1) * BN);

        CP_WAIT1();   // tile's stage (this thread's own adj words + its V words) done

        // ---- scores from own adj words ----
        {
            const int4 av = *(const int4*)&sAdj[stg][rowi * BN + jq];
            float4 p;
            float x;
            x = e1i + e2cur.x; x = fmaxf(x, ALPHA * x);
            p.x = (av.x > 0) ? tf32r(__expf(x)) : 0.f;
            x = e1i + e2cur.y; x = fmaxf(x, ALPHA * x);
            p.y = (av.y > 0) ? tf32r(__expf(x)) : 0.f;
            x = e1i + e2cur.z; x = fmaxf(x, ALPHA * x);
            p.z = (av.z > 0) ? tf32r(__expf(x)) : 0.f;
            x = e1i + e2cur.w; x = fmaxf(x, ALPHA * x);
            p.w = (av.w > 0) ? tf32r(__expf(x)) : 0.f;
            ssum += (p.x + p.y) + (p.z + p.w);
            *(float4*)&sP[buf][(rowi << 5) + ((jq + (rowi << 2)) & 31)] = p;
        }
        e2cur = e2nxt;

        __syncthreads();   // sP/sVT visible to all; MMA(tile-1) fully done

        // ---- issue loads for tile+NS-1 (overwrites stage (tile-1)%NS, now safe) ----
        {
            const int jt = tile + NS - 1;
            if (jt < NTILES) {
                const uint32_t so  = (uint32_t)(stgI * BM * BN * 4);
                const uint32_t vso = (uint32_t)(stgI * FO * BN * 4);
                cp16(adjDst + so, adjRow + jt * BN);
                cp16(vDst0 + vso, vsrc + jt * BN);
                cp16(vDst1 + vso, vsrc + jt * BN + 4);
            }
            CP_COMMIT();   // commit even if empty: keeps group count uniform
        }

        // ---- MMA: 4 k-steps x 2 n-tiles, m16n8k8 tf32 ----
        const float* cP = &sP[buf][0];
        const float* cV = &sVT[stg][0];
#pragma unroll
        for (int k = 0; k < 4; k++) {
            uint32_t afr[4];
            const int r0 = wm * 16 + lq;
            const int r1 = r0 + 8;
            const int c0 = k * 8 + lr;
            afr[0] = __float_as_uint(cP[(r0 << 5) + ((c0 + (r0 << 2)) & 31)]);
            afr[1] = __float_as_uint(cP[(r1 << 5) + ((c0 + (r1 << 2)) & 31)]);
            afr[2] = __float_as_uint(cP[(r0 << 5) + ((c0 + 4 + (r0 << 2)) & 31)]);
            afr[3] = __float_as_uint(cP[(r1 << 5) + ((c0 + 4 + (r1 << 2)) & 31)]);
#pragma unroll
            for (int nt = 0; nt < 2; nt++) {
                const int o = wn * 16 + nt * 8 + lq;
                const int s = (o & 7) << 2;
                const int jb = k * 8 + lr;
                const uint32_t b0 = __float_as_uint(cV[(o << 5) + (jb ^ s)]);
                const uint32_t b1 = __float_as_uint(cV[(o << 5) + ((jb + 4) ^ s)]);
                mma_tf32(acc[nt], afr, b0, b1);
            }
        }

        stg  = (stg == NS - 1) ? 0 : stg + 1;
        stgI = (stgI == NS - 1) ? 0 : stgI + 1;
    }

    // ---- row sums: reduce over 8 threads sharing a row ----
    ssum += __shfl_xor_sync(0xffffffffu, ssum, 1);
    ssum += __shfl_xor_sync(0xffffffffu, ssum, 2);
    ssum += __shfl_xor_sync(0xffffffffu, ssum, 4);
    if ((t & 7) == 0) sS[rowi] = ssum;
    __syncthreads();

    // ---- epilogue: normalize, ELU, store ----
    {
        const int r0 = wm * 16 + lq;
        const int r1 = r0 + 8;
        const float inv0 = 1.0f / sS[r0];
        const float inv1 = 1.0f / sS[r1];
        float* o0 = out + ((long)(b * Nn + i0 + r0)) * FO;
        float* o1 = out + ((long)(b * Nn + i0 + r1)) * FO;
#pragma unroll
        for (int nt = 0; nt < 2; nt++) {
            const int col = wn * 16 + nt * 8 + lr * 2;
            float2 q0, q1;
            float x;
            x = acc[nt][0] * inv0; q0.x = (x > 0.f) ? x : expm1f(x);
            x = acc[nt][1] * inv0; q0.y = (x > 0.f) ? x : expm1f(x);
            x = acc[nt][2] * inv1; q1.x = (x > 0.f) ? x : expm1f(x);
            x = acc[nt][3] * inv1; q1.y = (x > 0.f) ? x : expm1f(x);
            *(float2*)(o0 + col) = q0;
            *(float2*)(o1 + col) = q1;
        }
    }
}

// ---------------------------------------------------------------------------
extern "C" void kernel_launch(void* const* d_in, const int* in_sizes, int n_in,
                              void* d_out, int out_size)
{
    const float* h   = (const float*)d_in[0];
    const int*   adj = (const int*)d_in[1];
    const float* W   = (const float*)d_in[2];
    const float* a   = (const float*)d_in[3];
    float* out = (float*)d_out;

    gat_proj_kernel<<<(Bsz * Nn) / 32, 256>>>(h, W, a);
    gat_agg_mma_kernel<<<dim3(Nn / BM, Bsz), 256>>>(adj, out);
}

// round 14
// speedup vs baseline: 1.9908x; 1.0206x over previous
#include <cuda_runtime.h>
#include <cstdint>

#define Bsz 8
#define Nn 2048
#define FIN 128
#define FO 64
#define ALPHA 0.2f

#define BM 32
#define BN 32
#define NTILES (Nn / BN)   // 64
#define NS 3               // cp.async pipeline stages
#define PPITCH 258         // sP group pitch (words): ≡2 mod 8 → conflict-free LDS.64

// Scratch device globals (allocation-free per harness rules)
__device__ float g_WhT[Bsz * FO * Nn];   // transposed: [b][o][n]
__device__ float g_e1[Bsz * Nn];
__device__ float g_e2[Bsz * Nn];

// ---------------------------------------------------------------------------
// helpers
// ---------------------------------------------------------------------------
static __device__ __forceinline__ uint32_t smem_u32(const void* p) {
    uint32_t a;
    asm("{ .reg .u64 t; cvta.to.shared.u64 t, %1; cvt.u32.u64 %0, t; }"
        : "=r"(a) : "l"(p));
    return a;
}
static __device__ __forceinline__ void cp16(uint32_t dst, const void* src) {
    asm volatile("cp.async.cg.shared.global [%0], [%1], 16;"
                 :: "r"(dst), "l"(src) : "memory");
}
#define CP_COMMIT() asm volatile("cp.async.commit_group;" ::: "memory")
#define CP_WAIT1()  asm volatile("cp.async.wait_group 1;" ::: "memory")

static __device__ __forceinline__ float tf32r(float x) {
    uint32_t u;
    asm("cvt.rna.tf32.f32 %0, %1;" : "=r"(u) : "f"(x));
    return __uint_as_float(u);
}

static __device__ __forceinline__ void mma_tf32(
    float* d, uint32_t a0, uint32_t a1, uint32_t a2, uint32_t a3,
    uint32_t b0, uint32_t b1)
{
    asm volatile(
        "mma.sync.aligned.m16n8k8.row.col.f32.tf32.tf32.f32 "
        "{%0,%1,%2,%3},{%4,%5,%6,%7},{%8,%9},{%0,%1,%2,%3};"
        : "+f"(d[0]), "+f"(d[1]), "+f"(d[2]), "+f"(d[3])
        : "r"(a0), "r"(a1), "r"(a2), "r"(a3), "r"(b0), "r"(b1));
}

// ---------------------------------------------------------------------------
// Kernel 1: Wh = h @ W (written TRANSPOSED as WhT[b][o][n]); e1 = Wh·a1; e2 = Wh·a2
// ---------------------------------------------------------------------------
__global__ __launch_bounds__(256) void gat_proj_kernel(
    const float* __restrict__ h,
    const float* __restrict__ W,
    const float* __restrict__ a)
{
    __shared__ float sW[FIN * FO];   // 32 KB
    __shared__ float sT[FO * 33];    // transpose staging, pitch 33

    const int t = threadIdx.x;
#pragma unroll
    for (int r = 0; r < 8; r++)
        *(float4*)&sW[r * 1024 + t * 4] = *(const float4*)&W[r * 1024 + t * 4];

    const int warp = t >> 5;
    const int lane = t & 31;
    const int g0 = blockIdx.x * 32;
    const int i0 = g0 + warp * 4;

    const float a1l = a[lane];
    const float a1h = a[lane + 32];
    const float a2l = a[FO + lane];
    const float a2h = a[FO + 32 + lane];

    __syncthreads();

    float hr[4][4];
#pragma unroll
    for (int r = 0; r < 4; r++) {
        const float* hp = h + (long)(i0 + r) * FIN;
#pragma unroll
        for (int q = 0; q < 4; q++) hr[r][q] = hp[q * 32 + lane];
    }

    float acc[4][2];
#pragma unroll
    for (int r = 0; r < 4; r++) { acc[r][0] = 0.f; acc[r][1] = 0.f; }

#pragma unroll
    for (int q = 0; q < 4; q++) {
#pragma unroll
        for (int kk = 0; kk < 32; kk++) {
            const int k = q * 32 + kk;
            const float w0 = sW[k * FO + lane];
            const float w1 = sW[k * FO + 32 + lane];
#pragma unroll
            for (int r = 0; r < 4; r++) {
                const float hv = __shfl_sync(0xffffffffu, hr[r][q], kk);
                acc[r][0] = fmaf(hv, w0, acc[r][0]);
                acc[r][1] = fmaf(hv, w1, acc[r][1]);
            }
        }
    }

#pragma unroll
    for (int r = 0; r < 4; r++) {
        sT[lane * 33 + warp * 4 + r]        = acc[r][0];
        sT[(lane + 32) * 33 + warp * 4 + r] = acc[r][1];
    }

#pragma unroll
    for (int r = 0; r < 4; r++) {
        float e1 = acc[r][0] * a1l + acc[r][1] * a1h;
        float e2 = acc[r][0] * a2l + acc[r][1] * a2h;
#pragma unroll
        for (int off = 16; off > 0; off >>= 1) {
            e1 += __shfl_xor_sync(0xffffffffu, e1, off);
            e2 += __shfl_xor_sync(0xffffffffu, e2, off);
        }
        if (lane == 0) {
            g_e1[i0 + r] = e1;
            g_e2[i0 + r] = e2;
        }
    }

    __syncthreads();

    const int bb = g0 >> 11;
    const int il = g0 & (Nn - 1);
    const int oB = t >> 3;
    const int ii = (t & 7) * 4;
#pragma unroll
    for (int hf = 0; hf < 2; hf++) {
        const int o = hf * 32 + oB;
        float4 v;
        v.x = sT[o * 33 + ii + 0];
        v.y = sT[o * 33 + ii + 1];
        v.z = sT[o * 33 + ii + 2];
        v.w = sT[o * 33 + ii + 3];
        *(float4*)&g_WhT[((long)(bb * FO + o)) * Nn + il + ii] = v;
    }
}

// ---------------------------------------------------------------------------
// Kernel 2: masked-softmax aggregation via mma.sync tf32 (no-max softmax).
// grid (64, 8) = 512 CTAs, 256 threads. 3-stage cp.async pipeline for adj + V.
// sP uses (c&3)-grouped layout, pitch 258: A-fragments load as conflict-free
// LDS.64 pairs (a0,a2)/(a1,a3); P stored as 4x conflict-free STS.32.
// ---------------------------------------------------------------------------
__global__ __launch_bounds__(256, 4) void gat_agg_mma_kernel(
    const int* __restrict__ adj,
    float* __restrict__ out)
{
    __shared__ __align__(16) int   sAdj[NS][BM * BN];   // 12 KB
    __shared__ __align__(16) float sVT[NS][FO * BN];    // 24 KB (XOR-swizzled)
    __shared__ __align__(16) float sP[2][4 * PPITCH];   // ~8.1 KB (grouped by c&3)
    __shared__ float sS[BM];

    const int b  = blockIdx.y;
    const int i0 = blockIdx.x * BM;
    const int t  = threadIdx.x;
    const int warp = t >> 5;
    const int lane = t & 31;

    // score mapping: thread <-> (row, 4 j's)
    const int rowi = t >> 3;            // 0..31
    const int jq   = (t & 7) * 4;       // 0..28
    const int qP   = jq >> 2;           // 0..7 (q index into grouped sP)
    const float e1i = g_e1[b * Nn + i0 + rowi];
    const int*   adjRow = adj + ((long)(b * Nn + i0 + rowi)) * Nn + jq;
    const float* e2p    = g_e2 + b * Nn + jq;

    // V staging: thread <-> (o, 8 j's)
    const int vo = t >> 2;              // 0..63
    const int vq = (t & 3) * 8;         // 0..24
    const int vsw = (vo & 7) << 2;
    const float* vsrc = g_WhT + ((long)(b * FO + vo)) * Nn + vq;

    // per-thread fixed smem dst addresses
    const uint32_t adjDst = smem_u32(&sAdj[0][0]) + (uint32_t)((rowi * BN + jq) * 4);
    const uint32_t vDst0  = smem_u32(&sVT[0][0]) + (uint32_t)(((vo << 5) + (vq ^ vsw)) * 4);
    const uint32_t vDst1  = smem_u32(&sVT[0][0]) + (uint32_t)(((vo << 5) + ((vq + 4) ^ vsw)) * 4);

    // matmul mapping: warp tile 16 rows x 16 cols
    const int wm = warp & 1;
    const int wn = warp >> 1;           // 0..3
    const int lq = lane >> 2;
    const int lr = lane & 3;
    const int r0 = wm * 16 + lq;
    const int r1 = r0 + 8;
    // grouped-sP base offsets for A-fragment LDS.64 (k adds 2 words per step)
    const int aOff0 = lr * PPITCH + r0 * 8;
    const int aOff1 = lr * PPITCH + r1 * 8;

    float acc[2][4];
#pragma unroll
    for (int n = 0; n < 2; n++)
#pragma unroll
        for (int r = 0; r < 4; r++) acc[n][r] = 0.f;

    float ssum = 0.f;

    // ---- prologue: issue stages for tiles 0, 1 ----
#pragma unroll
    for (int s = 0; s < NS - 1; s++) {
        cp16(adjDst + (uint32_t)(s * BM * BN * 4), adjRow + s * BN);
        cp16(vDst0 + (uint32_t)(s * FO * BN * 4), vsrc + s * BN);
        cp16(vDst1 + (uint32_t)(s * FO * BN * 4), vsrc + s * BN + 4);
        CP_COMMIT();
    }
    float4 e2cur = *(const float4*)(e2p);

    int stg = 0;        // stage of current tile
    int stgI = NS - 1;  // stage being filled this iteration (tile t+NS-1)

    for (int tile = 0; tile < NTILES; tile++) {
        const int buf = tile & 1;

        // prefetch next tile's e2 into registers (L2-resident, tiny)
        float4 e2nxt;
        if (tile < NTILES - 1) e2nxt = *(const float4*)(e2p + (tile + 1) * BN);

        CP_WAIT1();   // tile's stage (this thread's own adj words + its V words) done

        // ---- scores from own adj words; store into grouped sP layout ----
        {
            const int4 av = *(const int4*)&sAdj[stg][rowi * BN + jq];
            float p0, p1, p2, p3;
            float x;
            x = e1i + e2cur.x; x = fmaxf(x, ALPHA * x);
            p0 = (av.x > 0) ? tf32r(__expf(x)) : 0.f;
            x = e1i + e2cur.y; x = fmaxf(x, ALPHA * x);
            p1 = (av.y > 0) ? tf32r(__expf(x)) : 0.f;
            x = e1i + e2cur.z; x = fmaxf(x, ALPHA * x);
            p2 = (av.z > 0) ? tf32r(__expf(x)) : 0.f;
            x = e1i + e2cur.w; x = fmaxf(x, ALPHA * x);
            p3 = (av.w > 0) ? tf32r(__expf(x)) : 0.f;
            ssum += (p0 + p1) + (p2 + p3);
            // col c = jq+g -> group g = c&3 (jq multiple of 4), q = qP
            float* pb = &sP[buf][rowi * 8 + qP];
            pb[0 * PPITCH] = p0;
            pb[1 * PPITCH] = p1;
            pb[2 * PPITCH] = p2;
            pb[3 * PPITCH] = p3;
        }
        e2cur = e2nxt;

        __syncthreads();   // sP/sVT visible to all; MMA(tile-1) fully done

        // ---- issue loads for tile+NS-1 (overwrites stage (tile-1)%NS, now safe) ----
        {
            const int jt = tile + NS - 1;
            if (jt < NTILES) {
                const uint32_t so  = (uint32_t)(stgI * BM * BN * 4);
                const uint32_t vso = (uint32_t)(stgI * FO * BN * 4);
                cp16(adjDst + so, adjRow + jt * BN);
                cp16(vDst0 + vso, vsrc + jt * BN);
                cp16(vDst1 + vso, vsrc + jt * BN + 4);
            }
            CP_COMMIT();   // commit even if empty: keeps group count uniform
        }

        // ---- MMA: 4 k-steps x 2 n-tiles, m16n8k8 tf32 ----
        // A-fragments: 2 conflict-free LDS.64 per k from grouped sP.
        const float* cP = &sP[buf][0];
        const float* cV = &sVT[stg][0];
#pragma unroll
        for (int k = 0; k < 4; k++) {
            const float2 a02 = *(const float2*)&cP[aOff0 + 2 * k];  // (a0, a2)
            const float2 a13 = *(const float2*)&cP[aOff1 + 2 * k];  // (a1, a3)
#pragma unroll
            for (int nt = 0; nt < 2; nt++) {
                const int o = wn * 16 + nt * 8 + lq;
                const int s = (o & 7) << 2;
                const int jb = k * 8 + lr;
                const uint32_t b0 = __float_as_uint(cV[(o << 5) + (jb ^ s)]);
                const uint32_t b1 = __float_as_uint(cV[(o << 5) + ((jb + 4) ^ s)]);
                mma_tf32(acc[nt],
                         __float_as_uint(a02.x), __float_as_uint(a13.x),
                         __float_as_uint(a02.y), __float_as_uint(a13.y),
                         b0, b1);
            }
        }

        stg  = (stg == NS - 1) ? 0 : stg + 1;
        stgI = (stgI == NS - 1) ? 0 : stgI + 1;
    }

    // ---- row sums: reduce over 8 threads sharing a row ----
    ssum += __shfl_xor_sync(0xffffffffu, ssum, 1);
    ssum += __shfl_xor_sync(0xffffffffu, ssum, 2);
    ssum += __shfl_xor_sync(0xffffffffu, ssum, 4);
    if ((t & 7) == 0) sS[rowi] = ssum;
    __syncthreads();

    // ---- epilogue: normalize, ELU, store ----
    {
        const float inv0 = 1.0f / sS[r0];
        const float inv1 = 1.0f / sS[r1];
        float* o0 = out + ((long)(b * Nn + i0 + r0)) * FO;
        float* o1 = out + ((long)(b * Nn + i0 + r1)) * FO;
#pragma unroll
        for (int nt = 0; nt < 2; nt++) {
            const int col = wn * 16 + nt * 8 + lr * 2;
            float2 q0, q1;
            float x;
            x = acc[nt][0] * inv0; q0.x = (x > 0.f) ? x : expm1f(x);
            x = acc[nt][1] * inv0; q0.y = (x > 0.f) ? x : expm1f(x);
            x = acc[nt][2] * inv1; q1.x = (x > 0.f) ? x : expm1f(x);
            x = acc[nt][3] * inv1; q1.y = (x > 0.f) ? x : expm1f(x);
            *(float2*)(o0 + col) = q0;
            *(float2*)(o1 + col) = q1;
        }
    }
}

// ---------------------------------------------------------------------------
extern "C" void kernel_launch(void* const* d_in, const int* in_sizes, int n_in,
                              void* d_out, int out_size)
{
    const float* h   = (const float*)d_in[0];
    const int*   adj = (const int*)d_in[1];
    const float* W   = (const float*)d_in[2];
    const float* a   = (const float*)d_in[3];
    float* out = (float*)d_out;

    gat_proj_kernel<<<(Bsz * Nn) / 32, 256>>>(h, W, a);
    gat_agg_mma_kernel<<<dim3(Nn / BM, Bsz), 256>>>(adj, out);
}

// round 15
// speedup vs baseline: 2.1206x; 1.0652x over previous
#include <cuda_runtime.h>
#include <cstdint>

#define Bsz 8
#define Nn 2048
#define FIN 128
#define FO 64
#define ALPHA 0.2f

#define BM 32
#define BN 32
#define NZ 2                       // j-split factor
#define NTILES (Nn / BN / NZ)      // 32 tiles per CTA
#define NS 3                       // cp.async pipeline stages
#define PPITCH 258                 // sP group pitch (words): ≡2 mod 8 → CF LDS.64

// Scratch device globals (allocation-free per harness rules)
__device__ float g_WhT[Bsz * FO * Nn];       // transposed: [b][o][n]
__device__ float g_e1[Bsz * Nn];
__device__ float g_e2[Bsz * Nn];
__device__ float g_pN[NZ][Bsz * Nn * FO];    // partial numerators (8 MB)
__device__ float g_pS[NZ][Bsz * Nn];         // partial row sums

// ---------------------------------------------------------------------------
// helpers
// ---------------------------------------------------------------------------
static __device__ __forceinline__ uint32_t smem_u32(const void* p) {
    uint32_t a;
    asm("{ .reg .u64 t; cvta.to.shared.u64 t, %1; cvt.u32.u64 %0, t; }"
        : "=r"(a) : "l"(p));
    return a;
}
static __device__ __forceinline__ void cp16(uint32_t dst, const void* src) {
    asm volatile("cp.async.cg.shared.global [%0], [%1], 16;"
                 :: "r"(dst), "l"(src) : "memory");
}
#define CP_COMMIT() asm volatile("cp.async.commit_group;" ::: "memory")
#define CP_WAIT1()  asm volatile("cp.async.wait_group 1;" ::: "memory")

static __device__ __forceinline__ float tf32r(float x) {
    uint32_t u;
    asm("cvt.rna.tf32.f32 %0, %1;" : "=r"(u) : "f"(x));
    return __uint_as_float(u);
}

static __device__ __forceinline__ void mma_tf32(
    float* d, uint32_t a0, uint32_t a1, uint32_t a2, uint32_t a3,
    uint32_t b0, uint32_t b1)
{
    asm volatile(
        "mma.sync.aligned.m16n8k8.row.col.f32.tf32.tf32.f32 "
        "{%0,%1,%2,%3},{%4,%5,%6,%7},{%8,%9},{%0,%1,%2,%3};"
        : "+f"(d[0]), "+f"(d[1]), "+f"(d[2]), "+f"(d[3])
        : "r"(a0), "r"(a1), "r"(a2), "r"(a3), "r"(b0), "r"(b1));
}

// ---------------------------------------------------------------------------
// Kernel 1: Wh = h @ W (written TRANSPOSED as WhT[b][o][n]); e1 = Wh·a1; e2 = Wh·a2
// ---------------------------------------------------------------------------
__global__ __launch_bounds__(256) void gat_proj_kernel(
    const float* __restrict__ h,
    const float* __restrict__ W,
    const float* __restrict__ a)
{
    __shared__ float sW[FIN * FO];   // 32 KB
    __shared__ float sT[FO * 33];    // transpose staging, pitch 33

    const int t = threadIdx.x;
#pragma unroll
    for (int r = 0; r < 8; r++)
        *(float4*)&sW[r * 1024 + t * 4] = *(const float4*)&W[r * 1024 + t * 4];

    const int warp = t >> 5;
    const int lane = t & 31;
    const int g0 = blockIdx.x * 32;
    const int i0 = g0 + warp * 4;

    const float a1l = a[lane];
    const float a1h = a[lane + 32];
    const float a2l = a[FO + lane];
    const float a2h = a[FO + 32 + lane];

    __syncthreads();

    float hr[4][4];
#pragma unroll
    for (int r = 0; r < 4; r++) {
        const float* hp = h + (long)(i0 + r) * FIN;
#pragma unroll
        for (int q = 0; q < 4; q++) hr[r][q] = hp[q * 32 + lane];
    }

    float acc[4][2];
#pragma unroll
    for (int r = 0; r < 4; r++) { acc[r][0] = 0.f; acc[r][1] = 0.f; }

#pragma unroll
    for (int q = 0; q < 4; q++) {
#pragma unroll
        for (int kk = 0; kk < 32; kk++) {
            const int k = q * 32 + kk;
            const float w0 = sW[k * FO + lane];
            const float w1 = sW[k * FO + 32 + lane];
#pragma unroll
            for (int r = 0; r < 4; r++) {
                const float hv = __shfl_sync(0xffffffffu, hr[r][q], kk);
                acc[r][0] = fmaf(hv, w0, acc[r][0]);
                acc[r][1] = fmaf(hv, w1, acc[r][1]);
            }
        }
    }

#pragma unroll
    for (int r = 0; r < 4; r++) {
        sT[lane * 33 + warp * 4 + r]        = acc[r][0];
        sT[(lane + 32) * 33 + warp * 4 + r] = acc[r][1];
    }

#pragma unroll
    for (int r = 0; r < 4; r++) {
        float e1 = acc[r][0] * a1l + acc[r][1] * a1h;
        float e2 = acc[r][0] * a2l + acc[r][1] * a2h;
#pragma unroll
        for (int off = 16; off > 0; off >>= 1) {
            e1 += __shfl_xor_sync(0xffffffffu, e1, off);
            e2 += __shfl_xor_sync(0xffffffffu, e2, off);
        }
        if (lane == 0) {
            g_e1[i0 + r] = e1;
            g_e2[i0 + r] = e2;
        }
    }

    __syncthreads();

    const int bb = g0 >> 11;
    const int il = g0 & (Nn - 1);
    const int oB = t >> 3;
    const int ii = (t & 7) * 4;
#pragma unroll
    for (int hf = 0; hf < 2; hf++) {
        const int o = hf * 32 + oB;
        float4 v;
        v.x = sT[o * 33 + ii + 0];
        v.y = sT[o * 33 + ii + 1];
        v.z = sT[o * 33 + ii + 2];
        v.w = sT[o * 33 + ii + 3];
        *(float4*)&g_WhT[((long)(bb * FO + o)) * Nn + il + ii] = v;
    }
}

// ---------------------------------------------------------------------------
// Kernel 2: PARTIAL masked-softmax aggregation via mma.sync tf32.
// grid (64, 8, 2) = 1024 CTAs, 256 threads. Each z-half handles 1024 j's
// (32 tiles). Writes unnormalized numerators + partial row sums.
// ---------------------------------------------------------------------------
__global__ __launch_bounds__(256, 4) void gat_agg_partial_kernel(
    const int* __restrict__ adj)
{
    __shared__ __align__(16) int   sAdj[NS][BM * BN];   // 12 KB
    __shared__ __align__(16) float sVT[NS][FO * BN];    // 24 KB (XOR-swizzled)
    __shared__ __align__(16) float sP[2][4 * PPITCH];   // ~8.1 KB (grouped by c&3)

    const int b  = blockIdx.y;
    const int i0 = blockIdx.x * BM;
    const int zh = blockIdx.z;          // j-half
    const int jz = zh * (Nn / NZ);      // j base offset (0 or 1024)
    const int t  = threadIdx.x;
    const int warp = t >> 5;
    const int lane = t & 31;

    // score mapping: thread <-> (row, 4 j's)
    const int rowi = t >> 3;            // 0..31
    const int jq   = (t & 7) * 4;       // 0..28
    const int qP   = jq >> 2;           // 0..7 (q index into grouped sP)
    const float e1i = g_e1[b * Nn + i0 + rowi];
    const int*   adjRow = adj + ((long)(b * Nn + i0 + rowi)) * Nn + jz + jq;
    const float* e2p    = g_e2 + b * Nn + jz + jq;

    // V staging: thread <-> (o, 8 j's)
    const int vo = t >> 2;              // 0..63
    const int vq = (t & 3) * 8;         // 0..24
    const int vsw = (vo & 7) << 2;
    const float* vsrc = g_WhT + ((long)(b * FO + vo)) * Nn + jz + vq;

    // per-thread fixed smem dst addresses
    const uint32_t adjDst = smem_u32(&sAdj[0][0]) + (uint32_t)((rowi * BN + jq) * 4);
    const uint32_t vDst0  = smem_u32(&sVT[0][0]) + (uint32_t)(((vo << 5) + (vq ^ vsw)) * 4);
    const uint32_t vDst1  = smem_u32(&sVT[0][0]) + (uint32_t)(((vo << 5) + ((vq + 4) ^ vsw)) * 4);

    // matmul mapping: warp tile 16 rows x 16 cols
    const int wm = warp & 1;
    const int wn = warp >> 1;           // 0..3
    const int lq = lane >> 2;
    const int lr = lane & 3;
    const int r0 = wm * 16 + lq;
    const int r1 = r0 + 8;
    const int aOff0 = lr * PPITCH + r0 * 8;
    const int aOff1 = lr * PPITCH + r1 * 8;

    float acc[2][4];
#pragma unroll
    for (int n = 0; n < 2; n++)
#pragma unroll
        for (int r = 0; r < 4; r++) acc[n][r] = 0.f;

    float ssum = 0.f;

    // ---- prologue: issue stages for tiles 0, 1 ----
#pragma unroll
    for (int s = 0; s < NS - 1; s++) {
        cp16(adjDst + (uint32_t)(s * BM * BN * 4), adjRow + s * BN);
        cp16(vDst0 + (uint32_t)(s * FO * BN * 4), vsrc + s * BN);
        cp16(vDst1 + (uint32_t)(s * FO * BN * 4), vsrc + s * BN + 4);
        CP_COMMIT();
    }
    float4 e2cur = *(const float4*)(e2p);

    int stg = 0;        // stage of current tile
    int stgI = NS - 1;  // stage being filled this iteration (tile t+NS-1)

    for (int tile = 0; tile < NTILES; tile++) {
        const int buf = tile & 1;

        // prefetch next tile's e2 into registers (L2-resident, tiny)
        float4 e2nxt;
        if (tile < NTILES - 1) e2nxt = *(const float4*)(e2p + (tile + 1) * BN);

        CP_WAIT1();   // tile's stage (own adj words + own V words) done

        // ---- scores from own adj words; store into grouped sP layout ----
        {
            const int4 av = *(const int4*)&sAdj[stg][rowi * BN + jq];
            float p0, p1, p2, p3;
            float x;
            x = e1i + e2cur.x; x = fmaxf(x, ALPHA * x);
            p0 = (av.x > 0) ? tf32r(__expf(x)) : 0.f;
            x = e1i + e2cur.y; x = fmaxf(x, ALPHA * x);
            p1 = (av.y > 0) ? tf32r(__expf(x)) : 0.f;
            x = e1i + e2cur.z; x = fmaxf(x, ALPHA * x);
            p2 = (av.z > 0) ? tf32r(__expf(x)) : 0.f;
            x = e1i + e2cur.w; x = fmaxf(x, ALPHA * x);
            p3 = (av.w > 0) ? tf32r(__expf(x)) : 0.f;
            ssum += (p0 + p1) + (p2 + p3);
            float* pb = &sP[buf][rowi * 8 + qP];
            pb[0 * PPITCH] = p0;
            pb[1 * PPITCH] = p1;
            pb[2 * PPITCH] = p2;
            pb[3 * PPITCH] = p3;
        }
        e2cur = e2nxt;

        __syncthreads();   // sP/sVT visible to all; MMA(tile-1) fully done

        // ---- issue loads for tile+NS-1 (overwrites stage (tile-1)%NS, now safe) ----
        {
            const int jt = tile + NS - 1;
            if (jt < NTILES) {
                const uint32_t so  = (uint32_t)(stgI * BM * BN * 4);
                const uint32_t vso = (uint32_t)(stgI * FO * BN * 4);
                cp16(adjDst + so, adjRow + jt * BN);
                cp16(vDst0 + vso, vsrc + jt * BN);
                cp16(vDst1 + vso, vsrc + jt * BN + 4);
            }
            CP_COMMIT();   // commit even if empty: keeps group count uniform
        }

        // ---- MMA: 4 k-steps x 2 n-tiles, m16n8k8 tf32 ----
        const float* cP = &sP[buf][0];
        const float* cV = &sVT[stg][0];
#pragma unroll
        for (int k = 0; k < 4; k++) {
            const float2 a02 = *(const float2*)&cP[aOff0 + 2 * k];  // (a0, a2)
            const float2 a13 = *(const float2*)&cP[aOff1 + 2 * k];  // (a1, a3)
#pragma unroll
            for (int nt = 0; nt < 2; nt++) {
                const int o = wn * 16 + nt * 8 + lq;
                const int s = (o & 7) << 2;
                const int jb = k * 8 + lr;
                const uint32_t b0 = __float_as_uint(cV[(o << 5) + (jb ^ s)]);
                const uint32_t b1 = __float_as_uint(cV[(o << 5) + ((jb + 4) ^ s)]);
                mma_tf32(acc[nt],
                         __float_as_uint(a02.x), __float_as_uint(a13.x),
                         __float_as_uint(a02.y), __float_as_uint(a13.y),
                         b0, b1);
            }
        }

        stg  = (stg == NS - 1) ? 0 : stg + 1;
        stgI = (stgI == NS - 1) ? 0 : stgI + 1;
    }

    // ---- partial row sums: reduce over 8 threads sharing a row, write gmem ----
    ssum += __shfl_xor_sync(0xffffffffu, ssum, 1);
    ssum += __shfl_xor_sync(0xffffffffu, ssum, 2);
    ssum += __shfl_xor_sync(0xffffffffu, ssum, 4);
    if ((t & 7) == 0) g_pS[zh][b * Nn + i0 + rowi] = ssum;

    // ---- epilogue: store raw partial numerators (no normalize) ----
    {
        float* o0 = &g_pN[zh][((long)(b * Nn + i0 + r0)) * FO];
        float* o1 = &g_pN[zh][((long)(b * Nn + i0 + r1)) * FO];
#pragma unroll
        for (int nt = 0; nt < 2; nt++) {
            const int col = wn * 16 + nt * 8 + lr * 2;
            *(float2*)(o0 + col) = make_float2(acc[nt][0], acc[nt][1]);
            *(float2*)(o1 + col) = make_float2(acc[nt][2], acc[nt][3]);
        }
    }
}

// ---------------------------------------------------------------------------
// Kernel 3: combine halves, normalize, ELU.
// 16384 rows x 64 cols; 1 thread per 4 cols -> 262144 threads, 1024 blocks.
// ---------------------------------------------------------------------------
__global__ __launch_bounds__(256) void gat_combine_kernel(float* __restrict__ out)
{
    const int idx = blockIdx.x * 256 + threadIdx.x;
    const int row = idx >> 4;
    const int cq  = (idx & 15) * 4;

    const float inv = 1.0f / (g_pS[0][row] + g_pS[1][row]);
    const float4 n0 = *(const float4*)&g_pN[0][(long)row * FO + cq];
    const float4 n1 = *(const float4*)&g_pN[1][(long)row * FO + cq];

    float4 o;
    float x;
    x = (n0.x + n1.x) * inv; o.x = (x > 0.f) ? x : expm1f(x);
    x = (n0.y + n1.y) * inv; o.y = (x > 0.f) ? x : expm1f(x);
    x = (n0.z + n1.z) * inv; o.z = (x > 0.f) ? x : expm1f(x);
    x = (n0.w + n1.w) * inv; o.w = (x > 0.f) ? x : expm1f(x);
    *(float4*)&out[(long)row * FO + cq] = o;
}

// ---------------------------------------------------------------------------
extern "C" void kernel_launch(void* const* d_in, const int* in_sizes, int n_in,
                              void* d_out, int out_size)
{
    const float* h   = (const float*)d_in[0];
    const int*   adj = (const int*)d_in[1];
    const float* W   = (const float*)d_in[2];
    const float* a   = (const float*)d_in[3];
    float* out = (float*)d_out;

    gat_proj_kernel<<<(Bsz * Nn) / 32, 256>>>(h, W, a);
    gat_agg_partial_kernel<<<dim3(Nn / BM, Bsz, NZ), 256>>>(adj);
    gat_combine_kernel<<<(Bsz * Nn * FO / 4) / 256, 256>>>(out);
}